// round 3
// baseline (speedup 1.0000x reference)
#include <cuda_runtime.h>
#include <cuda_bf16.h>
#include <math.h>

// ---------------------------------------------------------------------------
// TinyDiffusion MLP on GB300.
//   t_embed MLP + digit-embedding gather  -> tail buffer [B,128]
//   a0  = relu([x | tail] @ nw0^T + nb0)   K=20608 (fused concat)
//   a1  = relu(a0 @ nw1^T + nb1)           K=4096
//   out =       a1 @ nw2^T + nb2           K=4096, N=20480
// All GEMMs: A and W both K-contiguous (row-major [*, K]) -> "NT" SGEMM.
// HBM-bound: weights fp32 ~740MB; goal = stream them once at full BW.
// ---------------------------------------------------------------------------

#define BATCH      4096
#define LATENT_DIM 20480
#define TAIL_DIM   128          // 64 cond + 64 t_embed
#define IN_DIM     (LATENT_DIM + TAIL_DIM)   // 20608
#define HIDDEN     4096
#define TIME_DIM   64
#define COND_DIM   64

// scratch (device globals: allowed; runtime allocation is not)
__device__ float g_tail[BATCH * TAIL_DIM];
__device__ float g_a0[BATCH * HIDDEN];
__device__ float g_a1[BATCH * HIDDEN];

// ---------------------------------------------------------------------------
// Pre-kernel: time features -> 2-layer time MLP, plus digit embedding gather.
// One block per batch row, 64 threads (= TIME_DIM = COND_DIM).
// ---------------------------------------------------------------------------
__global__ void time_tail_kernel(const int* __restrict__ timesteps,
                                 const int* __restrict__ digits,
                                 const int* __restrict__ num_steps_p,
                                 const float* __restrict__ emb_table,
                                 const float* __restrict__ tw0,
                                 const float* __restrict__ tb0,
                                 const float* __restrict__ tw1,
                                 const float* __restrict__ tb1,
                                 float* __restrict__ tail)
{
    const int row = blockIdx.x;
    const int j   = threadIdx.x;            // 0..63

    __shared__ float h[TIME_DIM];

    const int ns = num_steps_p[0];
    const float denom = (float)((ns - 1) > 1 ? (ns - 1) : 1);
    const float t  = (float)timesteps[row] / denom;
    const float pi = 3.14159265358979323846f;
    const float f0 = t, f1 = t * t, f2 = sinf(pi * t), f3 = cosf(pi * t);

    // layer 0: h[j] = relu(feats . tw0[j,:] + tb0[j])
    float v = tb0[j]
            + f0 * tw0[j * 4 + 0] + f1 * tw0[j * 4 + 1]
            + f2 * tw0[j * 4 + 2] + f3 * tw0[j * 4 + 3];
    h[j] = fmaxf(v, 0.0f);
    __syncthreads();

    // layer 1: t_embed[j] = h . tw1[j,:] + tb1[j]
    float acc = tb1[j];
    #pragma unroll 8
    for (int i = 0; i < TIME_DIM; i++)
        acc += h[i] * tw1[j * TIME_DIM + i];

    // tail layout: [cond(64) | t_embed(64)]  (matches concat order after x)
    const int d = digits[row];
    tail[row * TAIL_DIM + j]            = emb_table[d * COND_DIM + j];
    tail[row * TAIL_DIM + COND_DIM + j] = acc;
}

// ---------------------------------------------------------------------------
// 128x128x16 fp32 SGEMM, C = act( A @ W^T + bias ).
// A: [M, lda] row-major (+ optional fused tail columns), W: [N, K] row-major.
// 256 threads, 8x8 microtile per thread, float4 global loads, register
// prefetch of the next K-slab, GROUP_M grid swizzle for L2 tile reuse.
// All problem dims are multiples of the tile dims -> no bounds checks.
// ---------------------------------------------------------------------------
#define BM 128
#define BN 128
#define BK 16
#define GROUP_M 16

template<bool FUSE_TAIL>
__device__ __forceinline__ float4 load_a(const float* __restrict__ A,
                                         const float* __restrict__ tail,
                                         int r, int k, int lda)
{
    if (FUSE_TAIL && k >= lda) {
        return *reinterpret_cast<const float4*>(tail + (size_t)r * TAIL_DIM + (k - lda));
    }
    return *reinterpret_cast<const float4*>(A + (size_t)r * lda + k);
}

template<bool FUSE_TAIL, bool RELU>
__global__ __launch_bounds__(256, 2)
void sgemm_kernel(const float* __restrict__ A,
                  const float* __restrict__ tail,
                  const float* __restrict__ W,
                  const float* __restrict__ bias,
                  float* __restrict__ C,
                  int M, int N, int K, int lda)
{
    __shared__ float As[BK][BM];
    __shared__ float Bs[BK][BN];

    // ---- grid swizzle: square-ish co-resident CTA groups for L2 reuse ----
    const int numPidM = M / BM;
    const int numPidN = N / BN;
    int pid = blockIdx.x;
    const int widthn   = GROUP_M * numPidN;
    const int groupId  = pid / widthn;
    const int firstM   = groupId * GROUP_M;
    const int gszM     = min(numPidM - firstM, GROUP_M);
    const int pidm     = firstM + (pid % gszM);
    const int pidn     = (pid % widthn) / gszM;

    const int tid = threadIdx.x;
    const int tx  = tid & 15;          // N direction
    const int ty  = tid >> 4;          // M direction

    // global-load mapping: each thread loads 2 float4 of A and 2 of W per slab
    const int loadRow = tid >> 2;          // 0..63
    const int loadK   = (tid & 3) << 2;    // 0,4,8,12

    const int aRow0 = pidm * BM + loadRow;
    const int wRow0 = pidn * BN + loadRow;

    float acc[8][8];
    #pragma unroll
    for (int i = 0; i < 8; i++)
        #pragma unroll
        for (int j = 0; j < 8; j++)
            acc[i][j] = 0.0f;

    float4 ra[2], rb[2];

    // preload first slab
    #pragma unroll
    for (int s = 0; s < 2; s++) {
        ra[s] = load_a<FUSE_TAIL>(A, tail, aRow0 + s * 64, loadK, lda);
        rb[s] = *reinterpret_cast<const float4*>(W + (size_t)(wRow0 + s * 64) * K + loadK);
    }
    #pragma unroll
    for (int s = 0; s < 2; s++) {
        As[loadK + 0][loadRow + s * 64] = ra[s].x;
        As[loadK + 1][loadRow + s * 64] = ra[s].y;
        As[loadK + 2][loadRow + s * 64] = ra[s].z;
        As[loadK + 3][loadRow + s * 64] = ra[s].w;
        Bs[loadK + 0][loadRow + s * 64] = rb[s].x;
        Bs[loadK + 1][loadRow + s * 64] = rb[s].y;
        Bs[loadK + 2][loadRow + s * 64] = rb[s].z;
        Bs[loadK + 3][loadRow + s * 64] = rb[s].w;
    }
    __syncthreads();

    for (int k0 = BK; k0 < K; k0 += BK) {
        // prefetch next slab into registers
        #pragma unroll
        for (int s = 0; s < 2; s++) {
            ra[s] = load_a<FUSE_TAIL>(A, tail, aRow0 + s * 64, k0 + loadK, lda);
            rb[s] = *reinterpret_cast<const float4*>(W + (size_t)(wRow0 + s * 64) * K + k0 + loadK);
        }

        // compute on current smem slab
        #pragma unroll
        for (int kk = 0; kk < BK; kk++) {
            float4 a0 = *reinterpret_cast<const float4*>(&As[kk][ty * 8]);
            float4 a1 = *reinterpret_cast<const float4*>(&As[kk][ty * 8 + 4]);
            float4 b0 = *reinterpret_cast<const float4*>(&Bs[kk][tx * 8]);
            float4 b1 = *reinterpret_cast<const float4*>(&Bs[kk][tx * 8 + 4]);
            float av[8] = {a0.x, a0.y, a0.z, a0.w, a1.x, a1.y, a1.z, a1.w};
            float bv[8] = {b0.x, b0.y, b0.z, b0.w, b1.x, b1.y, b1.z, b1.w};
            #pragma unroll
            for (int i = 0; i < 8; i++)
                #pragma unroll
                for (int j = 0; j < 8; j++)
                    acc[i][j] = fmaf(av[i], bv[j], acc[i][j]);
        }

        __syncthreads();
        #pragma unroll
        for (int s = 0; s < 2; s++) {
            As[loadK + 0][loadRow + s * 64] = ra[s].x;
            As[loadK + 1][loadRow + s * 64] = ra[s].y;
            As[loadK + 2][loadRow + s * 64] = ra[s].z;
            As[loadK + 3][loadRow + s * 64] = ra[s].w;
            Bs[loadK + 0][loadRow + s * 64] = rb[s].x;
            Bs[loadK + 1][loadRow + s * 64] = rb[s].y;
            Bs[loadK + 2][loadRow + s * 64] = rb[s].z;
            Bs[loadK + 3][loadRow + s * 64] = rb[s].w;
        }
        __syncthreads();
    }

    // last slab compute
    #pragma unroll
    for (int kk = 0; kk < BK; kk++) {
        float4 a0 = *reinterpret_cast<const float4*>(&As[kk][ty * 8]);
        float4 a1 = *reinterpret_cast<const float4*>(&As[kk][ty * 8 + 4]);
        float4 b0 = *reinterpret_cast<const float4*>(&Bs[kk][tx * 8]);
        float4 b1 = *reinterpret_cast<const float4*>(&Bs[kk][tx * 8 + 4]);
        float av[8] = {a0.x, a0.y, a0.z, a0.w, a1.x, a1.y, a1.z, a1.w};
        float bv[8] = {b0.x, b0.y, b0.z, b0.w, b1.x, b1.y, b1.z, b1.w};
        #pragma unroll
        for (int i = 0; i < 8; i++)
            #pragma unroll
            for (int j = 0; j < 8; j++)
                acc[i][j] = fmaf(av[i], bv[j], acc[i][j]);
    }

    // epilogue: bias + optional relu, float4 stores
    const int colBase = pidn * BN + tx * 8;
    float bcol[8];
    #pragma unroll
    for (int j = 0; j < 8; j++) bcol[j] = bias[colBase + j];

    #pragma unroll
    for (int i = 0; i < 8; i++) {
        const int row = pidm * BM + ty * 8 + i;
        float out[8];
        #pragma unroll
        for (int j = 0; j < 8; j++) {
            float v = acc[i][j] + bcol[j];
            out[j] = RELU ? fmaxf(v, 0.0f) : v;
        }
        float4* cp = reinterpret_cast<float4*>(C + (size_t)row * N + colBase);
        cp[0] = make_float4(out[0], out[1], out[2], out[3]);
        cp[1] = make_float4(out[4], out[5], out[6], out[7]);
    }
}

// ---------------------------------------------------------------------------
// Launch. Inputs (metadata order):
//  0 noisy_latent f32 [B,20,32,32]   1 digits i32 [B]   2 timesteps i32 [B]
//  3 num_steps i32 [1]               4 emb_table f32 [3,64]
//  5 tw0 [64,4]  6 tb0 [64]  7 tw1 [64,64]  8 tb1 [64]
//  9 nw0 [4096,20608] 10 nb0 [4096] 11 nw1 [4096,4096] 12 nb1 [4096]
// 13 nw2 [20480,4096] 14 nb2 [20480]
// ---------------------------------------------------------------------------
extern "C" void kernel_launch(void* const* d_in, const int* in_sizes, int n_in,
                              void* d_out, int out_size)
{
    const float* noisy     = (const float*)d_in[0];
    const int*   digits    = (const int*)  d_in[1];
    const int*   timesteps = (const int*)  d_in[2];
    const int*   num_steps = (const int*)  d_in[3];
    const float* emb       = (const float*)d_in[4];
    const float* tw0       = (const float*)d_in[5];
    const float* tb0       = (const float*)d_in[6];
    const float* tw1       = (const float*)d_in[7];
    const float* tb1       = (const float*)d_in[8];
    const float* nw0       = (const float*)d_in[9];
    const float* nb0       = (const float*)d_in[10];
    const float* nw1       = (const float*)d_in[11];
    const float* nb1       = (const float*)d_in[12];
    const float* nw2       = (const float*)d_in[13];
    const float* nb2       = (const float*)d_in[14];
    float*       out       = (float*)d_out;

    float *tail, *a0, *a1;
    cudaGetSymbolAddress((void**)&tail, g_tail);
    cudaGetSymbolAddress((void**)&a0,   g_a0);
    cudaGetSymbolAddress((void**)&a1,   g_a1);

    // 1) tail = [cond | t_embed]
    time_tail_kernel<<<BATCH, TIME_DIM>>>(timesteps, digits, num_steps,
                                          emb, tw0, tb0, tw1, tb1, tail);

    // 2) a0 = relu([x|tail] @ nw0^T + nb0)
    {
        int grid = (BATCH / BM) * (HIDDEN / BN);     // 32*32 = 1024
        sgemm_kernel<true, true><<<grid, 256>>>(noisy, tail, nw0, nb0, a0,
                                                BATCH, HIDDEN, IN_DIM, LATENT_DIM);
    }
    // 3) a1 = relu(a0 @ nw1^T + nb1)
    {
        int grid = (BATCH / BM) * (HIDDEN / BN);
        sgemm_kernel<false, true><<<grid, 256>>>(a0, nullptr, nw1, nb1, a1,
                                                 BATCH, HIDDEN, HIDDEN, HIDDEN);
    }
    // 4) out = a1 @ nw2^T + nb2
    {
        int grid = (BATCH / BM) * (LATENT_DIM / BN); // 32*160 = 5120
        sgemm_kernel<false, false><<<grid, 256>>>(a1, nullptr, nw2, nb2, out,
                                                  BATCH, LATENT_DIM, HIDDEN, HIDDEN);
    }
}

// round 5
// speedup vs baseline: 3.1508x; 3.1508x over previous
#include <cuda_runtime.h>
#include <math.h>
#include <stdint.h>

// ---------------------------------------------------------------------------
// TinyDiffusion MLP on GB300 — mma.sync tf32 path (tcgen05 unavailable on
// this toolchain's .target sm_103; mma.sync.m16n8k8.tf32 is sm_80+ portable).
//   tail = [digit_emb | time_mlp]
//   a0  = relu([x | tail] @ nw0^T + nb0)  K=20608 (concat fused per-slab)
//   a1  = relu(a0 @ nw1^T + nb1)          K=4096
//   out =       a1 @ nw2^T + nb2          K=4096, N=20480
// GEMM: 128x256x32 CTA tile, 8 warps (2x4), warp tile 64x64,
// cp.async.cg 4-stage ring, padded smem (stride 36) -> conflict-free frags,
// explicit cvt.rna.tf32.f32 rounding (avoids tf32 truncation bias ~1e-3).
// ---------------------------------------------------------------------------

#define BATCH      4096
#define LATENT_DIM 20480
#define TAIL_DIM   128
#define IN_DIM     20608
#define HIDDEN     4096
#define TIME_DIM   64
#define COND_DIM   64

#define BM 128
#define BN 256
#define BK 32
#define STAGES 4
#define SKA 36                       // floats per smem row (32 + 4 pad)
#define A_BYTES (BM * SKA * 4)       // 18432
#define B_BYTES (BN * SKA * 4)       // 36864
#define STG_BYTES (A_BYTES + B_BYTES)// 55296
#define SMEM_DYN (STAGES * STG_BYTES)// 221184
#define GROUP_M 16

__device__ float g_tail[BATCH * TAIL_DIM];
__device__ float g_a0[BATCH * HIDDEN];
__device__ float g_a1[BATCH * HIDDEN];

// ---------------- helpers ----------------
__device__ __forceinline__ uint32_t s2u(const void* p) {
    uint32_t a;
    asm("{ .reg .u64 t; cvta.to.shared.u64 t, %1; cvt.u32.u64 %0, t; }" : "=r"(a) : "l"(p));
    return a;
}
__device__ __forceinline__ void cp16(uint32_t dst, const void* src) {
    asm volatile("cp.async.cg.shared.global [%0], [%1], 16;" :: "r"(dst), "l"(src));
}
__device__ __forceinline__ uint32_t f2tf(float v) {
    uint32_t t;
    asm("cvt.rna.tf32.f32 %0, %1;" : "=r"(t) : "f"(v));
    return t;
}
__device__ __forceinline__ void mma8(float* c, const uint32_t* a, const uint32_t* b) {
    asm volatile("mma.sync.aligned.m16n8k8.row.col.f32.tf32.tf32.f32 "
                 "{%0,%1,%2,%3}, {%4,%5,%6,%7}, {%8,%9}, {%0,%1,%2,%3};"
                 : "+f"(c[0]), "+f"(c[1]), "+f"(c[2]), "+f"(c[3])
                 : "r"(a[0]), "r"(a[1]), "r"(a[2]), "r"(a[3]),
                   "r"(b[0]), "r"(b[1]));
}

// ---------------------------------------------------------------------------
// time features + 2-layer time MLP + digit embedding -> tail [B,128]
// ---------------------------------------------------------------------------
__global__ void time_tail_kernel(const int* __restrict__ timesteps,
                                 const int* __restrict__ digits,
                                 const int* __restrict__ num_steps_p,
                                 const float* __restrict__ emb_table,
                                 const float* __restrict__ tw0,
                                 const float* __restrict__ tb0,
                                 const float* __restrict__ tw1,
                                 const float* __restrict__ tb1,
                                 float* __restrict__ tail)
{
    const int row = blockIdx.x;
    const int j   = threadIdx.x;
    __shared__ float h[TIME_DIM];

    const int ns = num_steps_p[0];
    const float denom = (float)((ns - 1) > 1 ? (ns - 1) : 1);
    const float t = (float)timesteps[row] / denom;
    const float pi = 3.14159265358979323846f;
    const float f0 = t, f1 = t * t, f2 = sinf(pi * t), f3 = cosf(pi * t);

    float v = tb0[j] + f0 * tw0[j * 4 + 0] + f1 * tw0[j * 4 + 1]
                     + f2 * tw0[j * 4 + 2] + f3 * tw0[j * 4 + 3];
    h[j] = fmaxf(v, 0.0f);
    __syncthreads();

    float acc = tb1[j];
    #pragma unroll 8
    for (int i = 0; i < TIME_DIM; i++) acc += h[i] * tw1[j * TIME_DIM + i];

    const int d = digits[row];
    tail[row * TAIL_DIM + j]            = emb_table[d * COND_DIM + j];
    tail[row * TAIL_DIM + COND_DIM + j] = acc;
}

// ---------------------------------------------------------------------------
// tf32 mma.sync GEMM: C[M,N] = act(A[M,K] @ W[N,K]^T + bias)
// ---------------------------------------------------------------------------
template<bool FUSE, bool RELU>
__global__ __launch_bounds__(256, 1)
void gemm_mma(const float* __restrict__ A,
              const float* __restrict__ tailp,
              const float* __restrict__ W,
              const float* __restrict__ bias,
              float* __restrict__ C,
              int M, int N, int K, int lda)
{
    extern __shared__ char smem_raw[];

    const int tid  = threadIdx.x;
    const int wid  = tid >> 5;
    const int lane = tid & 31;
    const int wm   = wid >> 2;          // 0..1 (M dir, 64 rows each)
    const int wn   = wid & 3;           // 0..3 (N dir, 64 cols each)
    const int lr   = lane >> 2;         // 0..7
    const int lc   = lane & 3;          // 0..3

    // grid swizzle
    const int numPidM = M / BM;
    const int numPidN = N / BN;
    int pid = blockIdx.x;
    const int widthn  = GROUP_M * numPidN;
    const int groupId = pid / widthn;
    const int firstM  = groupId * GROUP_M;
    const int gszM    = min(numPidM - firstM, GROUP_M);
    const int pidm    = firstM + (pid % gszM);
    const int pidn    = (pid % widthn) / gszM;

    const int rowA0 = pidm * BM;
    const int rowB0 = pidn * BN;
    const int NSLAB = K / BK;

    const uint32_t smem_u = s2u(smem_raw);

    float acc[4][8][4];
    #pragma unroll
    for (int mt = 0; mt < 4; mt++)
        #pragma unroll
        for (int nt = 0; nt < 8; nt++)
            #pragma unroll
            for (int q = 0; q < 4; q++)
                acc[mt][nt][q] = 0.0f;

    // issue one K-slab's cp.async into its stage
    auto issue_slab = [&](int sl) {
        const int st = sl % STAGES;
        const uint32_t base = smem_u + st * STG_BYTES;
        const int k0 = sl * BK;
        #pragma unroll
        for (int t = 0; t < 4; t++) {                // A: 1024 x 16B
            int c = tid + t * 256;
            int r = c >> 3, kc = (c & 7) << 2;
            const float* src;
            if (FUSE && k0 >= lda)
                src = tailp + (size_t)(rowA0 + r) * TAIL_DIM + (k0 - lda) + kc;
            else
                src = A + (size_t)(rowA0 + r) * lda + k0 + kc;
            cp16(base + r * (SKA * 4) + kc * 4, src);
        }
        #pragma unroll
        for (int t = 0; t < 8; t++) {                // B: 2048 x 16B
            int c = tid + t * 256;
            int r = c >> 3, kc = (c & 7) << 2;
            const float* src = W + (size_t)(rowB0 + r) * K + k0 + kc;
            cp16(base + A_BYTES + r * (SKA * 4) + kc * 4, src);
        }
    };

    // prologue: stages 0..2
    issue_slab(0); asm volatile("cp.async.commit_group;" ::: "memory");
    issue_slab(1); asm volatile("cp.async.commit_group;" ::: "memory");
    issue_slab(2); asm volatile("cp.async.commit_group;" ::: "memory");

    for (int i = 0; i < NSLAB; i++) {
        asm volatile("cp.async.wait_group 2;" ::: "memory");
        __syncthreads();

        const int pre = i + STAGES - 1;
        if (pre < NSLAB) issue_slab(pre);
        asm volatile("cp.async.commit_group;" ::: "memory");

        // compute slab i from stage i%STAGES
        const float* sA = (const float*)(smem_raw + (i % STAGES) * STG_BYTES);
        const float* sB = (const float*)(smem_raw + (i % STAGES) * STG_BYTES + A_BYTES);

        #pragma unroll
        for (int ks = 0; ks < 4; ks++) {
            const int kb = ks * 8 + lc;
            uint32_t af[4][4], bf[8][2];
            #pragma unroll
            for (int mt = 0; mt < 4; mt++) {
                const int m0 = wm * 64 + mt * 16 + lr;
                af[mt][0] = f2tf(sA[m0 * SKA + kb]);
                af[mt][1] = f2tf(sA[(m0 + 8) * SKA + kb]);
                af[mt][2] = f2tf(sA[m0 * SKA + kb + 4]);
                af[mt][3] = f2tf(sA[(m0 + 8) * SKA + kb + 4]);
            }
            #pragma unroll
            for (int nt = 0; nt < 8; nt++) {
                const int n0 = wn * 64 + nt * 8 + lr;
                bf[nt][0] = f2tf(sB[n0 * SKA + kb]);
                bf[nt][1] = f2tf(sB[n0 * SKA + kb + 4]);
            }
            #pragma unroll
            for (int mt = 0; mt < 4; mt++)
                #pragma unroll
                for (int nt = 0; nt < 8; nt++)
                    mma8(acc[mt][nt], af[mt], bf[nt]);
        }
    }

    // epilogue: bias + optional relu, float2 stores
    #pragma unroll
    for (int nt = 0; nt < 8; nt++) {
        const int cb = wn * 64 + nt * 8 + lc * 2;
        const float2 bv = *reinterpret_cast<const float2*>(bias + rowB0 + cb);
        #pragma unroll
        for (int mt = 0; mt < 4; mt++) {
            const int r0 = rowA0 + wm * 64 + mt * 16 + lr;
            float2 o0, o1;
            o0.x = acc[mt][nt][0] + bv.x;  o0.y = acc[mt][nt][1] + bv.y;
            o1.x = acc[mt][nt][2] + bv.x;  o1.y = acc[mt][nt][3] + bv.y;
            if (RELU) {
                o0.x = fmaxf(o0.x, 0.0f); o0.y = fmaxf(o0.y, 0.0f);
                o1.x = fmaxf(o1.x, 0.0f); o1.y = fmaxf(o1.y, 0.0f);
            }
            *reinterpret_cast<float2*>(C + (size_t)r0 * N + rowB0 + cb)       = o0;
            *reinterpret_cast<float2*>(C + (size_t)(r0 + 8) * N + rowB0 + cb) = o1;
        }
    }
}

// ---------------------------------------------------------------------------
// Launch
// ---------------------------------------------------------------------------
extern "C" void kernel_launch(void* const* d_in, const int* in_sizes, int n_in,
                              void* d_out, int out_size)
{
    const float* noisy     = (const float*)d_in[0];
    const int*   digits    = (const int*)  d_in[1];
    const int*   timesteps = (const int*)  d_in[2];
    const int*   num_steps = (const int*)  d_in[3];
    const float* emb       = (const float*)d_in[4];
    const float* tw0       = (const float*)d_in[5];
    const float* tb0       = (const float*)d_in[6];
    const float* tw1       = (const float*)d_in[7];
    const float* tb1       = (const float*)d_in[8];
    const float* nw0       = (const float*)d_in[9];
    const float* nb0       = (const float*)d_in[10];
    const float* nw1       = (const float*)d_in[11];
    const float* nb1       = (const float*)d_in[12];
    const float* nw2       = (const float*)d_in[13];
    const float* nb2       = (const float*)d_in[14];
    float*       out       = (float*)d_out;

    float *tail, *a0, *a1;
    cudaGetSymbolAddress((void**)&tail, g_tail);
    cudaGetSymbolAddress((void**)&a0,   g_a0);
    cudaGetSymbolAddress((void**)&a1,   g_a1);

    cudaFuncSetAttribute(gemm_mma<true,  true >, cudaFuncAttributeMaxDynamicSharedMemorySize, SMEM_DYN);
    cudaFuncSetAttribute(gemm_mma<false, true >, cudaFuncAttributeMaxDynamicSharedMemorySize, SMEM_DYN);
    cudaFuncSetAttribute(gemm_mma<false, false>, cudaFuncAttributeMaxDynamicSharedMemorySize, SMEM_DYN);

    time_tail_kernel<<<BATCH, TIME_DIM>>>(timesteps, digits, num_steps,
                                          emb, tw0, tb0, tw1, tb1, tail);

    // a0 = relu([x|tail] @ nw0^T + nb0)
    gemm_mma<true, true><<<(BATCH / BM) * (HIDDEN / BN), 256, SMEM_DYN>>>(
        noisy, tail, nw0, nb0, a0, BATCH, HIDDEN, IN_DIM, LATENT_DIM);

    // a1 = relu(a0 @ nw1^T + nb1)
    gemm_mma<false, true><<<(BATCH / BM) * (HIDDEN / BN), 256, SMEM_DYN>>>(
        a0, nullptr, nw1, nb1, a1, BATCH, HIDDEN, HIDDEN, HIDDEN);

    // out = a1 @ nw2^T + nb2
    gemm_mma<false, false><<<(BATCH / BM) * (LATENT_DIM / BN), 256, SMEM_DYN>>>(
        a1, nullptr, nw2, nb2, out, BATCH, LATENT_DIM, HIDDEN, HIDDEN);
}

// round 6
// speedup vs baseline: 5.2197x; 1.6566x over previous
#include <cuda_runtime.h>
#include <cuda_fp16.h>
#include <math.h>
#include <stdint.h>

// ---------------------------------------------------------------------------
// TinyDiffusion MLP on GB300 — fp16 mma.sync (m16n8k16, f32 accum).
//   pre-pass: weights + noisy -> fp16 scratch (rne)
//   tail = [digit_emb | time_mlp]  (fp16)
//   a0  = relu([x|tail] @ nw0^T + nb0)  K=20608  -> fp16
//   a1  = relu(a0 @ nw1^T + nb1)        K=4096   -> fp16
//   out =       a1 @ nw2^T + nb2        K=4096, N=20480 -> fp32
// GEMM: 128x256x32 CTA tile, 512 thr / 16 warps (2x8), warp 64x32,
// 6-stage cp.async ring, ldmatrix.x4 fragments, 80B-padded smem rows.
// ---------------------------------------------------------------------------

#define BATCH      4096
#define LATENT_DIM 20480
#define TAIL_DIM   128
#define IN_DIM     20608
#define HIDDEN     4096
#define TIME_DIM   64
#define COND_DIM   64

#define BM 128
#define BN 256
#define BK 32                    // halves per slab (= 2 k16 steps)
#define STAGES 6
#define ROWB 80                  // bytes per smem row: 64B data + 16B pad
#define A_OFF 0
#define A_BYTES (BM * ROWB)      // 10240
#define B_OFF A_BYTES
#define B_BYTES (BN * ROWB)      // 20480
#define STG_BYTES (A_BYTES + B_BYTES)   // 30720
#define SMEM_DYN (STAGES * STG_BYTES)   // 184320
#define GROUP_M 16

// fp16 scratch (device globals: allowed; runtime allocation is not)
__device__ __align__(16) __half g_w0[(size_t)HIDDEN * IN_DIM];
__device__ __align__(16) __half g_w1[(size_t)HIDDEN * HIDDEN];
__device__ __align__(16) __half g_w2[(size_t)LATENT_DIM * HIDDEN];
__device__ __align__(16) __half g_x [(size_t)BATCH * LATENT_DIM];
__device__ __align__(16) __half g_tail[BATCH * TAIL_DIM];
__device__ __align__(16) __half g_a0[(size_t)BATCH * HIDDEN];
__device__ __align__(16) __half g_a1[(size_t)BATCH * HIDDEN];

// ---------------- helpers ----------------
__device__ __forceinline__ uint32_t s2u(const void* p) {
    uint32_t a;
    asm("{ .reg .u64 t; cvta.to.shared.u64 t, %1; cvt.u32.u64 %0, t; }" : "=r"(a) : "l"(p));
    return a;
}
__device__ __forceinline__ void cp16(uint32_t dst, const void* src) {
    asm volatile("cp.async.cg.shared.global [%0], [%1], 16;" :: "r"(dst), "l"(src));
}
__device__ __forceinline__ void ldsm4(uint32_t* r, uint32_t addr) {
    asm volatile("ldmatrix.sync.aligned.m8n8.x4.shared.b16 {%0,%1,%2,%3}, [%4];"
                 : "=r"(r[0]), "=r"(r[1]), "=r"(r[2]), "=r"(r[3]) : "r"(addr));
}
__device__ __forceinline__ void mma16(float* c, const uint32_t* a, uint32_t b0, uint32_t b1) {
    asm volatile("mma.sync.aligned.m16n8k16.row.col.f32.f16.f16.f32 "
                 "{%0,%1,%2,%3}, {%4,%5,%6,%7}, {%8,%9}, {%0,%1,%2,%3};"
                 : "+f"(c[0]), "+f"(c[1]), "+f"(c[2]), "+f"(c[3])
                 : "r"(a[0]), "r"(a[1]), "r"(a[2]), "r"(a[3]), "r"(b0), "r"(b1));
}

// ---------------------------------------------------------------------------
// fp32 -> fp16 (rne) elementwise, grid-stride over float4
// ---------------------------------------------------------------------------
__global__ void f2h_kernel(const float* __restrict__ in, __half* __restrict__ out, size_t n4)
{
    size_t i = blockIdx.x * (size_t)blockDim.x + threadIdx.x;
    size_t stride = (size_t)gridDim.x * blockDim.x;
    for (; i < n4; i += stride) {
        float4 v = reinterpret_cast<const float4*>(in)[i];
        __half2 h0 = __floats2half2_rn(v.x, v.y);
        __half2 h1 = __floats2half2_rn(v.z, v.w);
        uint32_t u0 = *reinterpret_cast<uint32_t*>(&h0);
        uint32_t u1 = *reinterpret_cast<uint32_t*>(&h1);
        reinterpret_cast<uint2*>(out)[i] = make_uint2(u0, u1);
    }
}

// ---------------------------------------------------------------------------
// time features + 2-layer time MLP + digit embedding -> fp16 tail [B,128]
// ---------------------------------------------------------------------------
__global__ void time_tail_kernel(const int* __restrict__ timesteps,
                                 const int* __restrict__ digits,
                                 const int* __restrict__ num_steps_p,
                                 const float* __restrict__ emb_table,
                                 const float* __restrict__ tw0,
                                 const float* __restrict__ tb0,
                                 const float* __restrict__ tw1,
                                 const float* __restrict__ tb1,
                                 __half* __restrict__ tail)
{
    const int row = blockIdx.x;
    const int j   = threadIdx.x;
    __shared__ float h[TIME_DIM];

    const int ns = num_steps_p[0];
    const float denom = (float)((ns - 1) > 1 ? (ns - 1) : 1);
    const float t = (float)timesteps[row] / denom;
    const float pi = 3.14159265358979323846f;
    const float f0 = t, f1 = t * t, f2 = sinf(pi * t), f3 = cosf(pi * t);

    float v = tb0[j] + f0 * tw0[j * 4 + 0] + f1 * tw0[j * 4 + 1]
                     + f2 * tw0[j * 4 + 2] + f3 * tw0[j * 4 + 3];
    h[j] = fmaxf(v, 0.0f);
    __syncthreads();

    float acc = tb1[j];
    #pragma unroll 8
    for (int i = 0; i < TIME_DIM; i++) acc += h[i] * tw1[j * TIME_DIM + i];

    const int d = digits[row];
    tail[row * TAIL_DIM + j]            = __float2half_rn(emb_table[d * COND_DIM + j]);
    tail[row * TAIL_DIM + COND_DIM + j] = __float2half_rn(acc);
}

// ---------------------------------------------------------------------------
// fp16 HMMA GEMM: C[M,N] = act(A[M,K] @ W[N,K]^T + bias)
// A,W fp16; bias fp32; C fp16 (HOUT) or fp32.
// ---------------------------------------------------------------------------
template<bool FUSE, bool RELU, bool HOUT>
__global__ __launch_bounds__(512, 1)
void gemm_h(const __half* __restrict__ A,
            const __half* __restrict__ tailp,
            const __half* __restrict__ W,
            const float* __restrict__ bias,
            void* __restrict__ Cout,
            int M, int N, int K, int lda)
{
    extern __shared__ char smem_raw[];
    const uint32_t smem_u = s2u(smem_raw);

    const int tid  = threadIdx.x;
    const int wid  = tid >> 5;
    const int lane = tid & 31;
    const int wm   = wid >> 3;            // 0..1  (64 rows)
    const int wn   = wid & 7;             // 0..7  (32 cols)

    // ldmatrix lane mapping: row-in-16, chunk(16B)-in-2
    const int lrow = (lane & 7) + ((lane >> 3) & 1) * 8;
    const int lch  = lane >> 4;           // 0..1

    // grid swizzle
    const int numPidM = M / BM;
    const int numPidN = N / BN;
    int pid = blockIdx.x;
    const int widthn  = GROUP_M * numPidN;
    const int groupId = pid / widthn;
    const int firstM  = groupId * GROUP_M;
    const int gszM    = min(numPidM - firstM, GROUP_M);
    const int pidm    = firstM + (pid % gszM);
    const int pidn    = (pid % widthn) / gszM;

    const int rowA0 = pidm * BM;
    const int rowB0 = pidn * BN;
    const int NSLAB = K / BK;

    float acc[4][4][4];
    #pragma unroll
    for (int mt = 0; mt < 4; mt++)
        #pragma unroll
        for (int nt = 0; nt < 4; nt++)
            #pragma unroll
            for (int q = 0; q < 4; q++) acc[mt][nt][q] = 0.0f;

    // cp.async mapping: A 512 chunks (1/thread), B 1024 chunks (2/thread)
    const int ar = tid >> 2, ac = tid & 3;
    auto issue_slab = [&](int sl) {
        if (sl >= NSLAB) return;
        const uint32_t base = smem_u + (sl % STAGES) * STG_BYTES;
        const int k0 = sl * BK;                       // halves
        // A
        {
            const __half* src;
            if (FUSE && k0 >= lda)
                src = tailp + (size_t)(rowA0 + ar) * TAIL_DIM + (k0 - lda) + ac * 8;
            else
                src = A + (size_t)(rowA0 + ar) * lda + k0 + ac * 8;
            cp16(base + A_OFF + ar * ROWB + ac * 16, src);
        }
        // B
        #pragma unroll
        for (int j = 0; j < 2; j++) {
            const int id = tid + j * 512;
            const int br = id >> 2, bc = id & 3;
            const __half* src = W + (size_t)(rowB0 + br) * K + k0 + bc * 8;
            cp16(base + B_OFF + br * ROWB + bc * 16, src);
        }
    };

    #pragma unroll
    for (int s = 0; s < STAGES - 1; s++) {
        issue_slab(s);
        asm volatile("cp.async.commit_group;" ::: "memory");
    }

    for (int i = 0; i < NSLAB; i++) {
        asm volatile("cp.async.wait_group %0;" :: "n"(STAGES - 2) : "memory");
        __syncthreads();

        issue_slab(i + STAGES - 1);
        asm volatile("cp.async.commit_group;" ::: "memory");

        const uint32_t sb = smem_u + (i % STAGES) * STG_BYTES;

        #pragma unroll
        for (int ks = 0; ks < 2; ks++) {
            uint32_t af[4][4], bf[2][4];
            #pragma unroll
            for (int mt = 0; mt < 4; mt++)
                ldsm4(af[mt], sb + A_OFF + (wm * 64 + mt * 16 + lrow) * ROWB + ks * 32 + lch * 16);
            #pragma unroll
            for (int p = 0; p < 2; p++)
                ldsm4(bf[p], sb + B_OFF + (wn * 32 + p * 16 + lrow) * ROWB + ks * 32 + lch * 16);
            #pragma unroll
            for (int mt = 0; mt < 4; mt++)
                #pragma unroll
                for (int nt = 0; nt < 4; nt++)
                    mma16(acc[mt][nt], af[mt], bf[nt >> 1][nt & 1], bf[nt >> 1][(nt & 1) + 2]);
        }
    }

    // epilogue
    const int lr = lane >> 2, lc = lane & 3;
    #pragma unroll
    for (int nt = 0; nt < 4; nt++) {
        const int col = rowB0 + wn * 32 + nt * 8 + lc * 2;
        const float2 bv = *reinterpret_cast<const float2*>(bias + col);
        #pragma unroll
        for (int mt = 0; mt < 4; mt++) {
            const int r0 = rowA0 + wm * 64 + mt * 16 + lr;
            float x0 = acc[mt][nt][0] + bv.x, x1 = acc[mt][nt][1] + bv.y;
            float x2 = acc[mt][nt][2] + bv.x, x3 = acc[mt][nt][3] + bv.y;
            if (RELU) {
                x0 = fmaxf(x0, 0.0f); x1 = fmaxf(x1, 0.0f);
                x2 = fmaxf(x2, 0.0f); x3 = fmaxf(x3, 0.0f);
            }
            if (HOUT) {
                __half* C = (__half*)Cout;
                __half2 h0 = __floats2half2_rn(x0, x1);
                __half2 h1 = __floats2half2_rn(x2, x3);
                *reinterpret_cast<__half2*>(C + (size_t)r0 * N + col)       = h0;
                *reinterpret_cast<__half2*>(C + (size_t)(r0 + 8) * N + col) = h1;
            } else {
                float* C = (float*)Cout;
                *reinterpret_cast<float2*>(C + (size_t)r0 * N + col)       = make_float2(x0, x1);
                *reinterpret_cast<float2*>(C + (size_t)(r0 + 8) * N + col) = make_float2(x2, x3);
            }
        }
    }
}

// ---------------------------------------------------------------------------
// Launch
// ---------------------------------------------------------------------------
extern "C" void kernel_launch(void* const* d_in, const int* in_sizes, int n_in,
                              void* d_out, int out_size)
{
    const float* noisy     = (const float*)d_in[0];
    const int*   digits    = (const int*)  d_in[1];
    const int*   timesteps = (const int*)  d_in[2];
    const int*   num_steps = (const int*)  d_in[3];
    const float* emb       = (const float*)d_in[4];
    const float* tw0       = (const float*)d_in[5];
    const float* tb0       = (const float*)d_in[6];
    const float* tw1       = (const float*)d_in[7];
    const float* tb1       = (const float*)d_in[8];
    const float* nw0       = (const float*)d_in[9];
    const float* nb0       = (const float*)d_in[10];
    const float* nw1       = (const float*)d_in[11];
    const float* nb1       = (const float*)d_in[12];
    const float* nw2       = (const float*)d_in[13];
    const float* nb2       = (const float*)d_in[14];
    float*       out       = (float*)d_out;

    __half *w0, *w1, *w2, *x, *tail, *a0, *a1;
    cudaGetSymbolAddress((void**)&w0,   g_w0);
    cudaGetSymbolAddress((void**)&w1,   g_w1);
    cudaGetSymbolAddress((void**)&w2,   g_w2);
    cudaGetSymbolAddress((void**)&x,    g_x);
    cudaGetSymbolAddress((void**)&tail, g_tail);
    cudaGetSymbolAddress((void**)&a0,   g_a0);
    cudaGetSymbolAddress((void**)&a1,   g_a1);

    cudaFuncSetAttribute(gemm_h<true,  true,  true >, cudaFuncAttributeMaxDynamicSharedMemorySize, SMEM_DYN);
    cudaFuncSetAttribute(gemm_h<false, true,  true >, cudaFuncAttributeMaxDynamicSharedMemorySize, SMEM_DYN);
    cudaFuncSetAttribute(gemm_h<false, false, false>, cudaFuncAttributeMaxDynamicSharedMemorySize, SMEM_DYN);

    // pre-pass: fp32 -> fp16
    f2h_kernel<<<2048, 256>>>(nw0,   w0, (size_t)HIDDEN * IN_DIM / 4);
    f2h_kernel<<<1024, 256>>>(nw1,   w1, (size_t)HIDDEN * HIDDEN / 4);
    f2h_kernel<<<2048, 256>>>(nw2,   w2, (size_t)LATENT_DIM * HIDDEN / 4);
    f2h_kernel<<<2048, 256>>>(noisy, x,  (size_t)BATCH * LATENT_DIM / 4);

    time_tail_kernel<<<BATCH, TIME_DIM>>>(timesteps, digits, num_steps,
                                          emb, tw0, tb0, tw1, tb1, tail);

    // a0 = relu([x|tail] @ nw0^T + nb0)
    gemm_h<true, true, true><<<(BATCH / BM) * (HIDDEN / BN), 512, SMEM_DYN>>>(
        x, tail, w0, nb0, a0, BATCH, HIDDEN, IN_DIM, LATENT_DIM);

    // a1 = relu(a0 @ nw1^T + nb1)
    gemm_h<false, true, true><<<(BATCH / BM) * (HIDDEN / BN), 512, SMEM_DYN>>>(
        a0, nullptr, w1, nb1, a1, BATCH, HIDDEN, HIDDEN, HIDDEN);

    // out = a1 @ nw2^T + nb2
    gemm_h<false, false, false><<<(BATCH / BM) * (LATENT_DIM / BN), 512, SMEM_DYN>>>(
        a1, nullptr, w2, nb2, out, BATCH, LATENT_DIM, HIDDEN, HIDDEN);
}

// round 7
// speedup vs baseline: 5.3862x; 1.0319x over previous
#include <cuda_runtime.h>
#include <cuda_fp16.h>
#include <math.h>
#include <stdint.h>

// ---------------------------------------------------------------------------
// TinyDiffusion MLP on GB300 — fp16 mma.sync (m16n8k16, f32 accum).
//   pre-pass: weights + noisy -> fp16 scratch (rne)
//   tail = [digit_emb | time_mlp]  (fp16)
//   a0  = relu([x|tail] @ nw0^T + nb0)  K=20608  -> fp16
//   a1  = relu(a0 @ nw1^T + nb1)        K=4096   -> fp16
//   out =       a1 @ nw2^T + nb2        K=4096, N=20480 -> fp32
// GEMM: 128x256x32 CTA tile, 256 thr / 8 warps (2x4), warp tile 64x64
// (halves smem fragment traffic vs 16x 64x32 warps: crossbar was co-binding),
// 6-stage cp.async ring, ldmatrix.x4, 80B-padded smem rows (conflict-free).
// ---------------------------------------------------------------------------

#define BATCH      4096
#define LATENT_DIM 20480
#define TAIL_DIM   128
#define IN_DIM     20608
#define HIDDEN     4096
#define TIME_DIM   64
#define COND_DIM   64

#define BM 128
#define BN 256
#define BK 32                    // halves per slab (= 2 k16 steps)
#define STAGES 6
#define ROWB 80                  // bytes per smem row: 64B data + 16B pad
#define A_OFF 0
#define A_BYTES (BM * ROWB)      // 10240
#define B_OFF A_BYTES
#define B_BYTES (BN * ROWB)      // 20480
#define STG_BYTES (A_BYTES + B_BYTES)   // 30720
#define SMEM_DYN (STAGES * STG_BYTES)   // 184320
#define GROUP_M 16

// fp16 scratch (device globals: allowed; runtime allocation is not)
__device__ __align__(16) __half g_w0[(size_t)HIDDEN * IN_DIM];
__device__ __align__(16) __half g_w1[(size_t)HIDDEN * HIDDEN];
__device__ __align__(16) __half g_w2[(size_t)LATENT_DIM * HIDDEN];
__device__ __align__(16) __half g_x [(size_t)BATCH * LATENT_DIM];
__device__ __align__(16) __half g_tail[BATCH * TAIL_DIM];
__device__ __align__(16) __half g_a0[(size_t)BATCH * HIDDEN];
__device__ __align__(16) __half g_a1[(size_t)BATCH * HIDDEN];

// ---------------- helpers ----------------
__device__ __forceinline__ uint32_t s2u(const void* p) {
    uint32_t a;
    asm("{ .reg .u64 t; cvta.to.shared.u64 t, %1; cvt.u32.u64 %0, t; }" : "=r"(a) : "l"(p));
    return a;
}
__device__ __forceinline__ void cp16(uint32_t dst, const void* src) {
    asm volatile("cp.async.cg.shared.global [%0], [%1], 16;" :: "r"(dst), "l"(src));
}
__device__ __forceinline__ void ldsm4(uint32_t* r, uint32_t addr) {
    asm volatile("ldmatrix.sync.aligned.m8n8.x4.shared.b16 {%0,%1,%2,%3}, [%4];"
                 : "=r"(r[0]), "=r"(r[1]), "=r"(r[2]), "=r"(r[3]) : "r"(addr));
}
__device__ __forceinline__ void mma16(float* c, const uint32_t* a, uint32_t b0, uint32_t b1) {
    asm volatile("mma.sync.aligned.m16n8k16.row.col.f32.f16.f16.f32 "
                 "{%0,%1,%2,%3}, {%4,%5,%6,%7}, {%8,%9}, {%0,%1,%2,%3};"
                 : "+f"(c[0]), "+f"(c[1]), "+f"(c[2]), "+f"(c[3])
                 : "r"(a[0]), "r"(a[1]), "r"(a[2]), "r"(a[3]), "r"(b0), "r"(b1));
}

// ---------------------------------------------------------------------------
// fp32 -> fp16 (rne) elementwise, grid-stride over float4
// ---------------------------------------------------------------------------
__global__ void f2h_kernel(const float* __restrict__ in, __half* __restrict__ out, size_t n4)
{
    size_t i = blockIdx.x * (size_t)blockDim.x + threadIdx.x;
    size_t stride = (size_t)gridDim.x * blockDim.x;
    for (; i < n4; i += stride) {
        float4 v = reinterpret_cast<const float4*>(in)[i];
        __half2 h0 = __floats2half2_rn(v.x, v.y);
        __half2 h1 = __floats2half2_rn(v.z, v.w);
        uint32_t u0 = *reinterpret_cast<uint32_t*>(&h0);
        uint32_t u1 = *reinterpret_cast<uint32_t*>(&h1);
        reinterpret_cast<uint2*>(out)[i] = make_uint2(u0, u1);
    }
}

// ---------------------------------------------------------------------------
// time features + 2-layer time MLP + digit embedding -> fp16 tail [B,128]
// ---------------------------------------------------------------------------
__global__ void time_tail_kernel(const int* __restrict__ timesteps,
                                 const int* __restrict__ digits,
                                 const int* __restrict__ num_steps_p,
                                 const float* __restrict__ emb_table,
                                 const float* __restrict__ tw0,
                                 const float* __restrict__ tb0,
                                 const float* __restrict__ tw1,
                                 const float* __restrict__ tb1,
                                 __half* __restrict__ tail)
{
    const int row = blockIdx.x;
    const int j   = threadIdx.x;
    __shared__ float h[TIME_DIM];

    const int ns = num_steps_p[0];
    const float denom = (float)((ns - 1) > 1 ? (ns - 1) : 1);
    const float t = (float)timesteps[row] / denom;
    const float pi = 3.14159265358979323846f;
    const float f0 = t, f1 = t * t, f2 = sinf(pi * t), f3 = cosf(pi * t);

    float v = tb0[j] + f0 * tw0[j * 4 + 0] + f1 * tw0[j * 4 + 1]
                     + f2 * tw0[j * 4 + 2] + f3 * tw0[j * 4 + 3];
    h[j] = fmaxf(v, 0.0f);
    __syncthreads();

    float acc = tb1[j];
    #pragma unroll 8
    for (int i = 0; i < TIME_DIM; i++) acc += h[i] * tw1[j * TIME_DIM + i];

    const int d = digits[row];
    tail[row * TAIL_DIM + j]            = __float2half_rn(emb_table[d * COND_DIM + j]);
    tail[row * TAIL_DIM + COND_DIM + j] = __float2half_rn(acc);
}

// ---------------------------------------------------------------------------
// fp16 HMMA GEMM: C[M,N] = act(A[M,K] @ W[N,K]^T + bias)
// A,W fp16; bias fp32; C fp16 (HOUT) or fp32.
// 8 warps (2x4), warp tile 64x64: acc[4 mt][8 ntg][4].
// ---------------------------------------------------------------------------
template<bool FUSE, bool RELU, bool HOUT>
__global__ __launch_bounds__(256, 1)
void gemm_h(const __half* __restrict__ A,
            const __half* __restrict__ tailp,
            const __half* __restrict__ W,
            const float* __restrict__ bias,
            void* __restrict__ Cout,
            int M, int N, int K, int lda)
{
    extern __shared__ char smem_raw[];
    const uint32_t smem_u = s2u(smem_raw);

    const int tid  = threadIdx.x;
    const int wid  = tid >> 5;
    const int lane = tid & 31;
    const int wm   = wid >> 2;            // 0..1  (64 rows)
    const int wn   = wid & 3;             // 0..3  (64 cols)

    // ldmatrix lane mapping: row-in-16, chunk(16B)-in-2
    const int lrow = (lane & 7) + ((lane >> 3) & 1) * 8;
    const int lch  = lane >> 4;           // 0..1

    // grid swizzle
    const int numPidM = M / BM;
    const int numPidN = N / BN;
    int pid = blockIdx.x;
    const int widthn  = GROUP_M * numPidN;
    const int groupId = pid / widthn;
    const int firstM  = groupId * GROUP_M;
    const int gszM    = min(numPidM - firstM, GROUP_M);
    const int pidm    = firstM + (pid % gszM);
    const int pidn    = (pid % widthn) / gszM;

    const int rowA0 = pidm * BM;
    const int rowB0 = pidn * BN;
    const int NSLAB = K / BK;

    float acc[4][8][4];
    #pragma unroll
    for (int mt = 0; mt < 4; mt++)
        #pragma unroll
        for (int nt = 0; nt < 8; nt++)
            #pragma unroll
            for (int q = 0; q < 4; q++) acc[mt][nt][q] = 0.0f;

    // cp.async mapping: A 512 chunks (2/thread), B 1024 chunks (4/thread)
    auto issue_slab = [&](int sl) {
        if (sl >= NSLAB) return;
        const uint32_t base = smem_u + (sl % STAGES) * STG_BYTES;
        const int k0 = sl * BK;                       // halves
        // A: 128 rows x 4 chunks
        #pragma unroll
        for (int j = 0; j < 2; j++) {
            const int id = tid + j * 256;
            const int r = id >> 2, c = id & 3;
            const __half* src;
            if (FUSE && k0 >= lda)
                src = tailp + (size_t)(rowA0 + r) * TAIL_DIM + (k0 - lda) + c * 8;
            else
                src = A + (size_t)(rowA0 + r) * lda + k0 + c * 8;
            cp16(base + A_OFF + r * ROWB + c * 16, src);
        }
        // B: 256 rows x 4 chunks
        #pragma unroll
        for (int j = 0; j < 4; j++) {
            const int id = tid + j * 256;
            const int r = id >> 2, c = id & 3;
            const __half* src = W + (size_t)(rowB0 + r) * K + k0 + c * 8;
            cp16(base + B_OFF + r * ROWB + c * 16, src);
        }
    };

    #pragma unroll
    for (int s = 0; s < STAGES - 1; s++) {
        issue_slab(s);
        asm volatile("cp.async.commit_group;" ::: "memory");
    }

    for (int i = 0; i < NSLAB; i++) {
        asm volatile("cp.async.wait_group %0;" :: "n"(STAGES - 2) : "memory");
        __syncthreads();

        issue_slab(i + STAGES - 1);
        asm volatile("cp.async.commit_group;" ::: "memory");

        const uint32_t sb = smem_u + (i % STAGES) * STG_BYTES;

        #pragma unroll
        for (int ks = 0; ks < 2; ks++) {
            uint32_t af[4][4], bf[4][4];
            #pragma unroll
            for (int mt = 0; mt < 4; mt++)
                ldsm4(af[mt], sb + A_OFF + (wm * 64 + mt * 16 + lrow) * ROWB + ks * 32 + lch * 16);
            #pragma unroll
            for (int p = 0; p < 4; p++)
                ldsm4(bf[p], sb + B_OFF + (wn * 64 + p * 16 + lrow) * ROWB + ks * 32 + lch * 16);
            #pragma unroll
            for (int mt = 0; mt < 4; mt++)
                #pragma unroll
                for (int nt = 0; nt < 8; nt++)
                    mma16(acc[mt][nt], af[mt], bf[nt >> 1][nt & 1], bf[nt >> 1][(nt & 1) + 2]);
        }
    }

    // epilogue: acc[mt][p*2+q] covers cols wn*64 + p*16 + q*8
    const int lr = lane >> 2, lc = lane & 3;
    #pragma unroll
    for (int nt = 0; nt < 8; nt++) {
        const int col = rowB0 + wn * 64 + (nt >> 1) * 16 + (nt & 1) * 8 + lc * 2;
        const float2 bv = *reinterpret_cast<const float2*>(bias + col);
        #pragma unroll
        for (int mt = 0; mt < 4; mt++) {
            const int r0 = rowA0 + wm * 64 + mt * 16 + lr;
            float x0 = acc[mt][nt][0] + bv.x, x1 = acc[mt][nt][1] + bv.y;
            float x2 = acc[mt][nt][2] + bv.x, x3 = acc[mt][nt][3] + bv.y;
            if (RELU) {
                x0 = fmaxf(x0, 0.0f); x1 = fmaxf(x1, 0.0f);
                x2 = fmaxf(x2, 0.0f); x3 = fmaxf(x3, 0.0f);
            }
            if (HOUT) {
                __half* C = (__half*)Cout;
                __half2 h0 = __floats2half2_rn(x0, x1);
                __half2 h1 = __floats2half2_rn(x2, x3);
                *reinterpret_cast<__half2*>(C + (size_t)r0 * N + col)       = h0;
                *reinterpret_cast<__half2*>(C + (size_t)(r0 + 8) * N + col) = h1;
            } else {
                float* C = (float*)Cout;
                *reinterpret_cast<float2*>(C + (size_t)r0 * N + col)       = make_float2(x0, x1);
                *reinterpret_cast<float2*>(C + (size_t)(r0 + 8) * N + col) = make_float2(x2, x3);
            }
        }
    }
}

// ---------------------------------------------------------------------------
// Launch
// ---------------------------------------------------------------------------
extern "C" void kernel_launch(void* const* d_in, const int* in_sizes, int n_in,
                              void* d_out, int out_size)
{
    const float* noisy     = (const float*)d_in[0];
    const int*   digits    = (const int*)  d_in[1];
    const int*   timesteps = (const int*)  d_in[2];
    const int*   num_steps = (const int*)  d_in[3];
    const float* emb       = (const float*)d_in[4];
    const float* tw0       = (const float*)d_in[5];
    const float* tb0       = (const float*)d_in[6];
    const float* tw1       = (const float*)d_in[7];
    const float* tb1       = (const float*)d_in[8];
    const float* nw0       = (const float*)d_in[9];
    const float* nb0       = (const float*)d_in[10];
    const float* nw1       = (const float*)d_in[11];
    const float* nb1       = (const float*)d_in[12];
    const float* nw2       = (const float*)d_in[13];
    const float* nb2       = (const float*)d_in[14];
    float*       out       = (float*)d_out;

    __half *w0, *w1, *w2, *x, *tail, *a0, *a1;
    cudaGetSymbolAddress((void**)&w0,   g_w0);
    cudaGetSymbolAddress((void**)&w1,   g_w1);
    cudaGetSymbolAddress((void**)&w2,   g_w2);
    cudaGetSymbolAddress((void**)&x,    g_x);
    cudaGetSymbolAddress((void**)&tail, g_tail);
    cudaGetSymbolAddress((void**)&a0,   g_a0);
    cudaGetSymbolAddress((void**)&a1,   g_a1);

    cudaFuncSetAttribute(gemm_h<true,  true,  true >, cudaFuncAttributeMaxDynamicSharedMemorySize, SMEM_DYN);
    cudaFuncSetAttribute(gemm_h<false, true,  true >, cudaFuncAttributeMaxDynamicSharedMemorySize, SMEM_DYN);
    cudaFuncSetAttribute(gemm_h<false, false, false>, cudaFuncAttributeMaxDynamicSharedMemorySize, SMEM_DYN);

    // pre-pass: fp32 -> fp16
    f2h_kernel<<<2048, 256>>>(nw0,   w0, (size_t)HIDDEN * IN_DIM / 4);
    f2h_kernel<<<1024, 256>>>(nw1,   w1, (size_t)HIDDEN * HIDDEN / 4);
    f2h_kernel<<<2048, 256>>>(nw2,   w2, (size_t)LATENT_DIM * HIDDEN / 4);
    f2h_kernel<<<2048, 256>>>(noisy, x,  (size_t)BATCH * LATENT_DIM / 4);

    time_tail_kernel<<<BATCH, TIME_DIM>>>(timesteps, digits, num_steps,
                                          emb, tw0, tb0, tw1, tb1, tail);

    // a0 = relu([x|tail] @ nw0^T + nb0)
    gemm_h<true, true, true><<<(BATCH / BM) * (HIDDEN / BN), 256, SMEM_DYN>>>(
        x, tail, w0, nb0, a0, BATCH, HIDDEN, IN_DIM, LATENT_DIM);

    // a1 = relu(a0 @ nw1^T + nb1)
    gemm_h<false, true, true><<<(BATCH / BM) * (HIDDEN / BN), 256, SMEM_DYN>>>(
        a0, nullptr, w1, nb1, a1, BATCH, HIDDEN, HIDDEN, HIDDEN);

    // out = a1 @ nw2^T + nb2
    gemm_h<false, false, false><<<(BATCH / BM) * (LATENT_DIM / BN), 256, SMEM_DYN>>>(
        a1, nullptr, w2, nb2, out, BATCH, LATENT_DIM, HIDDEN, HIDDEN);
}